// round 16
// baseline (speedup 1.0000x reference)
#include <cuda_runtime.h>
#include <cuda_bf16.h>
#include <cuda_fp16.h>
#include <cstdint>

// EdgePredictor, factorized:
//   Stage 1: fp16 1-pass GEMM  Y[100000,256] = X@W  (fp32 acc), TILE_M=64.
//            Measured AT the sm_103 legacy-HMMA chip ceiling (~182 TF/s). Frozen.
//   Stage 2: out[e] = relu(A[row] + B[col]) @ W2 + b2, 4 lanes/edge, fp16 W2,
//            two 8-edge groups (16-load batch), 128-thread blocks;
//            __launch_bounds__(128,10) -> 48 regs, 10 blocks/SM = 40 warps
//            (R14 measured optimum was 52 regs / 36 warps; R15 proved
//            warps >> per-warp batch residency).

#define ND  128
#define MAX_NODES 100000
#define TILE_M 64

__device__ __half g_Ah[(size_t)MAX_NODES * ND];   // 25.6 MB
__device__ __half g_Bh[(size_t)MAX_NODES * ND];   // 25.6 MB

// SMEM layout (dynamic, 112.8 KB)
#define SM_W    0          // 65536  W' fp16 [n=256][k=128], 256B rows, swizzled
#define SM_ARAW 65536      // 32768  raw fp32 X tile (64 x 128 f32)
#define SM_AH   98304      // 16384  fp16 X tile (64 x 128), swizzled
#define SM_B1   114688     // 512
#define SMEM_TOTAL 115200

// XOR swizzle for 256-byte rows: byte bits [4:6] ^= row bits [8:10]
#define SWZ(x) ((x) ^ (((x) >> 4) & 0x70))

static __device__ __forceinline__ uint32_t smem_u32(const void* p) {
    uint32_t a;
    asm("{ .reg .u64 t; cvta.to.shared.u64 t, %1; cvt.u32.u64 %0, t; }" : "=r"(a) : "l"(p));
    return a;
}

#define LDSM4(r, addr)                                                          \
    asm volatile("ldmatrix.sync.aligned.m8n8.x4.shared.b16 {%0,%1,%2,%3}, [%4];"\
        : "=r"((r)[0]), "=r"((r)[1]), "=r"((r)[2]), "=r"((r)[3]) : "r"(addr))

#define MMA16816F(d, a, b)                                                      \
    asm volatile("mma.sync.aligned.m16n8k16.row.col.f32.f16.f16.f32 "           \
        "{%0,%1,%2,%3}, {%4,%5,%6,%7}, {%8,%9}, {%0,%1,%2,%3};"                 \
        : "+f"((d)[0]), "+f"((d)[1]), "+f"((d)[2]), "+f"((d)[3])                \
        : "r"((a)[0]), "r"((a)[1]), "r"((a)[2]), "r"((a)[3]),                   \
          "r"((b)[0]), "r"((b)[1]))

#define CP_ASYNC16(dst, src, nbytes)                                            \
    asm volatile("cp.async.cg.shared.global [%0], [%1], 16, %2;"                \
        :: "r"(dst), "l"(src), "r"(nbytes))
#define CP_COMMIT() asm volatile("cp.async.commit_group;" ::: "memory")
#define CP_WAIT0()  asm volatile("cp.async.wait_group 0;" ::: "memory")

// ---------------------------------------------------------------------------
// Stage 1: persistent pipelined fp16 GEMM. 512 threads, 16 warps (2m x 8n),
// CTA tile 64x256, warp tile 32x32. At legacy-HMMA ceiling — unchanged.
// ---------------------------------------------------------------------------
__global__ __launch_bounds__(512, 1) void gemm_kernel(
    const float* __restrict__ x, const float* __restrict__ W1,
    const float* __restrict__ b1, int nnodes, int ntiles)
{
    extern __shared__ char smem[];
    const uint32_t sb = smem_u32(smem);
    const int tid  = threadIdx.x;
    const int lane = tid & 31;
    const int w    = tid >> 5;
    const int warp_m = w & 1;    // 2 groups of 32 rows
    const int warp_n = w >> 1;   // 8 groups of 32 cols

    const int prow = tid >> 5;          // + it*16
    const int pc4  = tid & 31;

    int tile = blockIdx.x;
    {
        long base = (long)tile * TILE_M;
        #pragma unroll
        for (int it = 0; it < 4; it++) {
            int row = prow + it * 16;
            long node = base + row;
            const char* src = (const char*)(x + node * (long)ND) + pc4 * 16;
            uint32_t dst = sb + SM_ARAW + row * 512 + pc4 * 16;
            int nb = (tile < ntiles && node < nnodes) ? 16 : 0;
            if (nb == 0) src = (const char*)x;
            CP_ASYNC16(dst, src, nb);
        }
        CP_COMMIT();
    }

    // W'[n][k]: n<128 -> W1[k][n] ; n>=128 -> W1[128+k][n-128]
    #pragma unroll
    for (int i = tid; i < 256 * 128; i += 512) {
        int r = i >> 7, c = i & 127;
        int k = (r < 128) ? r : (r - 128);
        int n = (r < 128) ? c : (c + 128);
        __half hv = __float2half_rn(W1[i]);
        *(__half*)(smem + SM_W + SWZ((uint32_t)(n * 256 + k * 2))) = hv;
    }
    if (tid < 128) ((float*)(smem + SM_B1))[tid] = b1[tid];

    CP_WAIT0();
    __syncthreads();

    const int a_row = (lane & 15);
    const int a_ko  = (lane >> 4) << 4;
    const int b_row = (lane & 7) + ((lane >> 4) << 3);
    const int b_ko  = ((lane >> 3) & 1) << 4;

    for (; tile < ntiles; tile += gridDim.x) {
        const long base = (long)tile * TILE_M;

        #pragma unroll
        for (int it = 0; it < 4; it++) {
            int row = prow + it * 16;
            float4 v = *(const float4*)(smem + SM_ARAW + row * 512 + pc4 * 16);
            __half2 h01 = __floats2half2_rn(v.x, v.y);
            __half2 h23 = __floats2half2_rn(v.z, v.w);
            uint2 hp;
            hp.x = *(uint32_t*)&h01; hp.y = *(uint32_t*)&h23;
            *(uint2*)(smem + SM_AH + SWZ((uint32_t)(row * 256 + pc4 * 8))) = hp;
        }
        __syncthreads();

        {
            int nxt = tile + gridDim.x;
            long nbase = (long)nxt * TILE_M;
            #pragma unroll
            for (int it = 0; it < 4; it++) {
                int row = prow + it * 16;
                long node = nbase + row;
                const char* src = (const char*)(x + node * (long)ND) + pc4 * 16;
                uint32_t dst = sb + SM_ARAW + row * 512 + pc4 * 16;
                int nb = (nxt < ntiles && node < nnodes) ? 16 : 0;
                if (nb == 0) src = (const char*)x;
                CP_ASYNC16(dst, src, nb);
            }
            CP_COMMIT();
        }

        float acc[2][4][4];
        #pragma unroll
        for (int ms = 0; ms < 2; ms++)
            #pragma unroll
            for (int ns = 0; ns < 4; ns++)
                #pragma unroll
                for (int e = 0; e < 4; e++) acc[ms][ns][e] = 0.f;

        #pragma unroll
        for (int ks = 0; ks < 8; ks++) {
            uint32_t av[2][4], bv[8];
            #pragma unroll
            for (int ms = 0; ms < 2; ms++) {
                uint32_t ab = SWZ((uint32_t)((warp_m * 32 + ms * 16 + a_row) * 256
                                             + ks * 32 + a_ko));
                LDSM4(av[ms], sb + SM_AH + ab);
            }
            #pragma unroll
            for (int bj = 0; bj < 2; bj++) {
                uint32_t bb = SWZ((uint32_t)((warp_n * 32 + bj * 16 + b_row) * 256
                                             + ks * 32 + b_ko));
                LDSM4(&bv[bj * 4], sb + SM_W + bb);
            }
            #pragma unroll
            for (int ms = 0; ms < 2; ms++)
                #pragma unroll
                for (int ns = 0; ns < 4; ns++)
                    MMA16816F(acc[ms][ns], av[ms], &bv[ns * 2]);
        }

        __half* dsth = (warp_n < 4) ? g_Ah : g_Bh;
        const int colbase = (warp_n & 3) * 32 + 2 * (lane & 3);
        const int rowbase = warp_m * 32 + (lane >> 2);
        const float* b1s = (const float*)(smem + SM_B1);

        #pragma unroll
        for (int ms = 0; ms < 2; ms++) {
            #pragma unroll
            for (int ns = 0; ns < 4; ns++) {
                const int col = colbase + ns * 8;
                float bias0 = 0.f, bias1 = 0.f;
                if (warp_n < 4) { bias0 = b1s[col]; bias1 = b1s[col + 1]; }
                long node0 = base + rowbase + ms * 16;
                if (node0 < nnodes)
                    *(__half2*)(dsth + node0 * (long)ND + col) =
                        __floats2half2_rn(acc[ms][ns][0] + bias0, acc[ms][ns][1] + bias1);
                long node1 = node0 + 8;
                if (node1 < nnodes)
                    *(__half2*)(dsth + node1 * (long)ND + col) =
                        __floats2half2_rn(acc[ms][ns][2] + bias0, acc[ms][ns][3] + bias1);
            }
        }

        CP_WAIT0();
        __syncthreads();
    }
}

// ---------------------------------------------------------------------------
// Stage 2: 4 lanes/edge, TWO 8-edge groups per warp iteration. 128-thread
// blocks; __launch_bounds__(128, 10) -> <=48 regs, 10 blocks/SM = 40 warps.
// ---------------------------------------------------------------------------
__global__ __launch_bounds__(128, 10) void edge_kernel(
    const int* __restrict__ ei,        // [2, E] int32
    const float* __restrict__ W2,      // [128, 2]
    const float* __restrict__ b2,      // [2]
    float* __restrict__ out,           // [E, 2]
    int E)
{
    __shared__ __half wa_h[ND];
    __shared__ __half wb_h[ND];
    const int tid = threadIdx.x;
    if (tid < ND) {
        wa_h[tid] = __float2half_rn(W2[tid * 2 + 0]);
        wb_h[tid] = __float2half_rn(W2[tid * 2 + 1]);
    }
    __syncthreads();

    const int lane = tid & 31;
    const int t    = lane & 3;
    const int sub  = lane >> 2;
    const float b20 = __ldg(b2), b21 = __ldg(b2 + 1);
    const __half2 z2 = __float2half2_rn(0.f);

    const int warp   = (blockIdx.x * blockDim.x + tid) >> 5;
    const int nwarps = (gridDim.x * blockDim.x) >> 5;

    const uint4* wa4 = (const uint4*)wa_h;   // 16 chunks x 8 half
    const uint4* wb4 = (const uint4*)wb_h;

    for (int eb = warp * 16; eb < E; eb += nwarps * 16) {
        const int e0 = eb + sub;           // E % 16 == 0
        const int e1 = eb + 8 + sub;
        const int r0 = __ldg(ei + e0);
        const int c0 = __ldg(ei + (size_t)E + e0);
        const int r1 = __ldg(ei + e1);
        const int c1 = __ldg(ei + (size_t)E + e1);

        const uint4* pa0 = (const uint4*)(g_Ah + (size_t)r0 * ND);
        const uint4* pb0 = (const uint4*)(g_Bh + (size_t)c0 * ND);
        const uint4* pa1 = (const uint4*)(g_Ah + (size_t)r1 * ND);
        const uint4* pb1 = (const uint4*)(g_Bh + (size_t)c1 * ND);

        uint4 A0[4], B0[4], A1[4], B1[4];
        #pragma unroll
        for (int i = 0; i < 4; i++) {
            const int ch = i * 4 + t;
            A0[i] = __ldg(pa0 + ch);
            B0[i] = __ldg(pb0 + ch);
            A1[i] = __ldg(pa1 + ch);
            B1[i] = __ldg(pb1 + ch);
        }

        float o00 = 0.f, o01 = 0.f, o10 = 0.f, o11 = 0.f;
        #pragma unroll
        for (int i = 0; i < 4; i++) {
            const int ch = i * 4 + t;
            uint4 wav = wa4[ch];
            uint4 wbv = wb4[ch];
            const __half2* wap = (const __half2*)&wav;
            const __half2* wbp = (const __half2*)&wbv;
            const __half2* a0p = (const __half2*)&A0[i];
            const __half2* b0p = (const __half2*)&B0[i];
            const __half2* a1p = (const __half2*)&A1[i];
            const __half2* b1p = (const __half2*)&B1[i];

            #pragma unroll
            for (int q = 0; q < 4; q++) {
                float2 wa = __half22float2(wap[q]);
                float2 wb = __half22float2(wbp[q]);
                float2 f0 = __half22float2(__hmax2(__hadd2(a0p[q], b0p[q]), z2));
                float2 f1 = __half22float2(__hmax2(__hadd2(a1p[q], b1p[q]), z2));
                o00 = fmaf(f0.x, wa.x, fmaf(f0.y, wa.y, o00));
                o01 = fmaf(f0.x, wb.x, fmaf(f0.y, wb.y, o01));
                o10 = fmaf(f1.x, wa.x, fmaf(f1.y, wa.y, o10));
                o11 = fmaf(f1.x, wb.x, fmaf(f1.y, wb.y, o11));
            }
        }

        o00 += __shfl_xor_sync(0xFFFFFFFFu, o00, 1);
        o00 += __shfl_xor_sync(0xFFFFFFFFu, o00, 2);
        o01 += __shfl_xor_sync(0xFFFFFFFFu, o01, 1);
        o01 += __shfl_xor_sync(0xFFFFFFFFu, o01, 2);
        o10 += __shfl_xor_sync(0xFFFFFFFFu, o10, 1);
        o10 += __shfl_xor_sync(0xFFFFFFFFu, o10, 2);
        o11 += __shfl_xor_sync(0xFFFFFFFFu, o11, 1);
        o11 += __shfl_xor_sync(0xFFFFFFFFu, o11, 2);

        if (t == 0) {
            *(float2*)(out + 2 * (size_t)e0) = make_float2(o00 + b20, o01 + b21);
            *(float2*)(out + 2 * (size_t)e1) = make_float2(o10 + b20, o11 + b21);
        }
    }
}

// ---------------------------------------------------------------------------
extern "C" void kernel_launch(void* const* d_in, const int* in_sizes, int n_in,
                              void* d_out, int out_size)
{
    const float* x  = (const float*)d_in[0];      // [N,128]
    const int*   ei = (const int*)d_in[1];        // [2,E] int32
    const float* W1 = (const float*)d_in[2];      // [256,128]
    const float* b1 = (const float*)d_in[3];      // [128]
    const float* W2 = (const float*)d_in[4];      // [128,2]
    const float* b2 = (const float*)d_in[5];      // [2]
    float*       out = (float*)d_out;             // [E,2]

    const int nnodes = in_sizes[0] / ND;
    const int E      = in_sizes[1] / 2;
    const int ntiles = (nnodes + TILE_M - 1) / TILE_M;

    cudaFuncSetAttribute(gemm_kernel, cudaFuncAttributeMaxDynamicSharedMemorySize,
                         SMEM_TOTAL);

    gemm_kernel<<<148, 512, SMEM_TOTAL>>>(x, W1, b1, nnodes, ntiles);
    edge_kernel<<<(E + 63) / 64, 128>>>(ei, W2, b2, out, E);
}

// round 17
// speedup vs baseline: 1.0167x; 1.0167x over previous
#include <cuda_runtime.h>
#include <cuda_bf16.h>
#include <cuda_fp16.h>
#include <cstdint>

// EdgePredictor, factorized:
//   Stage 1: fp16 1-pass GEMM  Y[100000,256] = X@W  (fp32 acc), TILE_M=64.
//            At the sm_103 legacy-HMMA chip ceiling (~24 cyc/HMMA). Frozen (R14).
//   Stage 2: out[e] = relu(A[row] + B[col]) @ W2 + b2.
//            8 lanes/edge x 4 groups: every LDG.128 covers 4 edges x 128B =
//            4 FULL L1 lines (wavefront floor), 16 loads/lane in flight (MLP=16).

#define ND  128
#define MAX_NODES 100000
#define TILE_M 64

__device__ __half g_Ah[(size_t)MAX_NODES * ND];   // 25.6 MB
__device__ __half g_Bh[(size_t)MAX_NODES * ND];   // 25.6 MB

// SMEM layout (dynamic, 112.8 KB)
#define SM_W    0          // 65536  W' fp16 [n=256][k=128], 256B rows, swizzled
#define SM_ARAW 65536      // 32768  raw fp32 X tile (64 x 128 f32)
#define SM_AH   98304      // 16384  fp16 X tile (64 x 128), swizzled
#define SM_B1   114688     // 512
#define SMEM_TOTAL 115200

// XOR swizzle for 256-byte rows: byte bits [4:6] ^= row bits [8:10]
#define SWZ(x) ((x) ^ (((x) >> 4) & 0x70))

static __device__ __forceinline__ uint32_t smem_u32(const void* p) {
    uint32_t a;
    asm("{ .reg .u64 t; cvta.to.shared.u64 t, %1; cvt.u32.u64 %0, t; }" : "=r"(a) : "l"(p));
    return a;
}

#define LDSM4(r, addr)                                                          \
    asm volatile("ldmatrix.sync.aligned.m8n8.x4.shared.b16 {%0,%1,%2,%3}, [%4];"\
        : "=r"((r)[0]), "=r"((r)[1]), "=r"((r)[2]), "=r"((r)[3]) : "r"(addr))

#define MMA16816F(d, a, b)                                                      \
    asm volatile("mma.sync.aligned.m16n8k16.row.col.f32.f16.f16.f32 "           \
        "{%0,%1,%2,%3}, {%4,%5,%6,%7}, {%8,%9}, {%0,%1,%2,%3};"                 \
        : "+f"((d)[0]), "+f"((d)[1]), "+f"((d)[2]), "+f"((d)[3])                \
        : "r"((a)[0]), "r"((a)[1]), "r"((a)[2]), "r"((a)[3]),                   \
          "r"((b)[0]), "r"((b)[1]))

#define CP_ASYNC16(dst, src, nbytes)                                            \
    asm volatile("cp.async.cg.shared.global [%0], [%1], 16, %2;"                \
        :: "r"(dst), "l"(src), "r"(nbytes))
#define CP_COMMIT() asm volatile("cp.async.commit_group;" ::: "memory")
#define CP_WAIT0()  asm volatile("cp.async.wait_group 0;" ::: "memory")

// ---------------------------------------------------------------------------
// Stage 1: persistent pipelined fp16 GEMM. 512 threads, 16 warps (2m x 8n),
// CTA tile 64x256, warp tile 32x32. At legacy-HMMA ceiling — unchanged (R14).
// ---------------------------------------------------------------------------
__global__ __launch_bounds__(512, 1) void gemm_kernel(
    const float* __restrict__ x, const float* __restrict__ W1,
    const float* __restrict__ b1, int nnodes, int ntiles)
{
    extern __shared__ char smem[];
    const uint32_t sb = smem_u32(smem);
    const int tid  = threadIdx.x;
    const int lane = tid & 31;
    const int w    = tid >> 5;
    const int warp_m = w & 1;    // 2 groups of 32 rows
    const int warp_n = w >> 1;   // 8 groups of 32 cols

    const int prow = tid >> 5;          // + it*16
    const int pc4  = tid & 31;

    int tile = blockIdx.x;
    {
        long base = (long)tile * TILE_M;
        #pragma unroll
        for (int it = 0; it < 4; it++) {
            int row = prow + it * 16;
            long node = base + row;
            const char* src = (const char*)(x + node * (long)ND) + pc4 * 16;
            uint32_t dst = sb + SM_ARAW + row * 512 + pc4 * 16;
            int nb = (tile < ntiles && node < nnodes) ? 16 : 0;
            if (nb == 0) src = (const char*)x;
            CP_ASYNC16(dst, src, nb);
        }
        CP_COMMIT();
    }

    // W'[n][k]: n<128 -> W1[k][n] ; n>=128 -> W1[128+k][n-128]
    #pragma unroll
    for (int i = tid; i < 256 * 128; i += 512) {
        int r = i >> 7, c = i & 127;
        int k = (r < 128) ? r : (r - 128);
        int n = (r < 128) ? c : (c + 128);
        __half hv = __float2half_rn(W1[i]);
        *(__half*)(smem + SM_W + SWZ((uint32_t)(n * 256 + k * 2))) = hv;
    }
    if (tid < 128) ((float*)(smem + SM_B1))[tid] = b1[tid];

    CP_WAIT0();
    __syncthreads();

    const int a_row = (lane & 15);
    const int a_ko  = (lane >> 4) << 4;
    const int b_row = (lane & 7) + ((lane >> 4) << 3);
    const int b_ko  = ((lane >> 3) & 1) << 4;

    for (; tile < ntiles; tile += gridDim.x) {
        const long base = (long)tile * TILE_M;

        #pragma unroll
        for (int it = 0; it < 4; it++) {
            int row = prow + it * 16;
            float4 v = *(const float4*)(smem + SM_ARAW + row * 512 + pc4 * 16);
            __half2 h01 = __floats2half2_rn(v.x, v.y);
            __half2 h23 = __floats2half2_rn(v.z, v.w);
            uint2 hp;
            hp.x = *(uint32_t*)&h01; hp.y = *(uint32_t*)&h23;
            *(uint2*)(smem + SM_AH + SWZ((uint32_t)(row * 256 + pc4 * 8))) = hp;
        }
        __syncthreads();

        {
            int nxt = tile + gridDim.x;
            long nbase = (long)nxt * TILE_M;
            #pragma unroll
            for (int it = 0; it < 4; it++) {
                int row = prow + it * 16;
                long node = nbase + row;
                const char* src = (const char*)(x + node * (long)ND) + pc4 * 16;
                uint32_t dst = sb + SM_ARAW + row * 512 + pc4 * 16;
                int nb = (nxt < ntiles && node < nnodes) ? 16 : 0;
                if (nb == 0) src = (const char*)x;
                CP_ASYNC16(dst, src, nb);
            }
            CP_COMMIT();
        }

        float acc[2][4][4];
        #pragma unroll
        for (int ms = 0; ms < 2; ms++)
            #pragma unroll
            for (int ns = 0; ns < 4; ns++)
                #pragma unroll
                for (int e = 0; e < 4; e++) acc[ms][ns][e] = 0.f;

        #pragma unroll
        for (int ks = 0; ks < 8; ks++) {
            uint32_t av[2][4], bv[8];
            #pragma unroll
            for (int ms = 0; ms < 2; ms++) {
                uint32_t ab = SWZ((uint32_t)((warp_m * 32 + ms * 16 + a_row) * 256
                                             + ks * 32 + a_ko));
                LDSM4(av[ms], sb + SM_AH + ab);
            }
            #pragma unroll
            for (int bj = 0; bj < 2; bj++) {
                uint32_t bb = SWZ((uint32_t)((warp_n * 32 + bj * 16 + b_row) * 256
                                             + ks * 32 + b_ko));
                LDSM4(&bv[bj * 4], sb + SM_W + bb);
            }
            #pragma unroll
            for (int ms = 0; ms < 2; ms++)
                #pragma unroll
                for (int ns = 0; ns < 4; ns++)
                    MMA16816F(acc[ms][ns], av[ms], &bv[ns * 2]);
        }

        __half* dsth = (warp_n < 4) ? g_Ah : g_Bh;
        const int colbase = (warp_n & 3) * 32 + 2 * (lane & 3);
        const int rowbase = warp_m * 32 + (lane >> 2);
        const float* b1s = (const float*)(smem + SM_B1);

        #pragma unroll
        for (int ms = 0; ms < 2; ms++) {
            #pragma unroll
            for (int ns = 0; ns < 4; ns++) {
                const int col = colbase + ns * 8;
                float bias0 = 0.f, bias1 = 0.f;
                if (warp_n < 4) { bias0 = b1s[col]; bias1 = b1s[col + 1]; }
                long node0 = base + rowbase + ms * 16;
                if (node0 < nnodes)
                    *(__half2*)(dsth + node0 * (long)ND + col) =
                        __floats2half2_rn(acc[ms][ns][0] + bias0, acc[ms][ns][1] + bias1);
                long node1 = node0 + 8;
                if (node1 < nnodes)
                    *(__half2*)(dsth + node1 * (long)ND + col) =
                        __floats2half2_rn(acc[ms][ns][2] + bias0, acc[ms][ns][3] + bias1);
            }
        }

        CP_WAIT0();
        __syncthreads();
    }
}

// ---------------------------------------------------------------------------
// Stage 2: 8 lanes/edge (t8 = lane&7 -> chunk; sub4 = lane>>3 -> edge), 4
// groups of 4 edges per warp = 16 edges/iter. Each LDG.128 covers 4 edges x
// 128B = 4 full L1 lines; 16 loads/lane issued before consumption (MLP=16).
// ---------------------------------------------------------------------------
__global__ __launch_bounds__(128) void edge_kernel(
    const int* __restrict__ ei,        // [2, E] int32
    const float* __restrict__ W2,      // [128, 2]
    const float* __restrict__ b2,      // [2]
    float* __restrict__ out,           // [E, 2]
    int E)
{
    __shared__ __half wa_h[ND];
    __shared__ __half wb_h[ND];
    const int tid = threadIdx.x;
    if (tid < ND) {
        wa_h[tid] = __float2half_rn(W2[tid * 2 + 0]);
        wb_h[tid] = __float2half_rn(W2[tid * 2 + 1]);
    }
    __syncthreads();

    const int lane = tid & 31;
    const int t8   = lane & 7;        // chunk within 128B half-row (0..7)
    const int sub4 = lane >> 3;       // edge within group (0..3)
    const float b20 = __ldg(b2), b21 = __ldg(b2 + 1);
    const __half2 z2 = __float2half2_rn(0.f);

    const int warp   = (blockIdx.x * blockDim.x + tid) >> 5;
    const int nwarps = (gridDim.x * blockDim.x) >> 5;

    const uint4* wa4 = (const uint4*)wa_h;   // 16 chunks x 8 half
    const uint4* wb4 = (const uint4*)wb_h;

    for (int eb = warp * 16; eb < E; eb += nwarps * 16) {
        // 4 groups of 4 edges; this lane serves edge eb + g*4 + sub4 in group g
        int r[4], c[4];
        #pragma unroll
        for (int g = 0; g < 4; g++) {
            const int e = eb + g * 4 + sub4;    // E % 16 == 0
            r[g] = __ldg(ei + e);
            c[g] = __ldg(ei + (size_t)E + e);
        }

        // issue all 16 gathers (each instruction: 4 edges x full 128B line)
        uint4 A0[4], A1[4], B0[4], B1[4];
        #pragma unroll
        for (int g = 0; g < 4; g++) {
            const uint4* pa = (const uint4*)(g_Ah + (size_t)r[g] * ND);
            const uint4* pb = (const uint4*)(g_Bh + (size_t)c[g] * ND);
            A0[g] = __ldg(pa + t8);
            A1[g] = __ldg(pa + t8 + 8);
            B0[g] = __ldg(pb + t8);
            B1[g] = __ldg(pb + t8 + 8);
        }

        // weights for this lane's chunks (shared across all 4 groups)
        uint4 wA0 = wa4[t8], wA1 = wa4[t8 + 8];
        uint4 wB0 = wb4[t8], wB1 = wb4[t8 + 8];
        const __half2* wa0p = (const __half2*)&wA0;
        const __half2* wa1p = (const __half2*)&wA1;
        const __half2* wb0p = (const __half2*)&wB0;
        const __half2* wb1p = (const __half2*)&wB1;

        float o0[4], o1[4];
        #pragma unroll
        for (int g = 0; g < 4; g++) { o0[g] = 0.f; o1[g] = 0.f; }

        #pragma unroll
        for (int g = 0; g < 4; g++) {
            const __half2* a0p = (const __half2*)&A0[g];
            const __half2* b0p = (const __half2*)&B0[g];
            const __half2* a1p = (const __half2*)&A1[g];
            const __half2* b1p = (const __half2*)&B1[g];
            #pragma unroll
            for (int q = 0; q < 4; q++) {
                float2 f0 = __half22float2(__hmax2(__hadd2(a0p[q], b0p[q]), z2));
                float2 f1 = __half22float2(__hmax2(__hadd2(a1p[q], b1p[q]), z2));
                float2 wa0 = __half22float2(wa0p[q]);
                float2 wa1 = __half22float2(wa1p[q]);
                float2 wb0 = __half22float2(wb0p[q]);
                float2 wb1 = __half22float2(wb1p[q]);
                o0[g] = fmaf(f0.x, wa0.x, fmaf(f0.y, wa0.y, o0[g]));
                o0[g] = fmaf(f1.x, wa1.x, fmaf(f1.y, wa1.y, o0[g]));
                o1[g] = fmaf(f0.x, wb0.x, fmaf(f0.y, wb0.y, o1[g]));
                o1[g] = fmaf(f1.x, wb1.x, fmaf(f1.y, wb1.y, o1[g]));
            }
        }

        // reduce across the 8 lanes of each edge (lanes with equal sub4)
        #pragma unroll
        for (int g = 0; g < 4; g++) {
            o0[g] += __shfl_xor_sync(0xFFFFFFFFu, o0[g], 1);
            o0[g] += __shfl_xor_sync(0xFFFFFFFFu, o0[g], 2);
            o0[g] += __shfl_xor_sync(0xFFFFFFFFu, o0[g], 4);
            o1[g] += __shfl_xor_sync(0xFFFFFFFFu, o1[g], 1);
            o1[g] += __shfl_xor_sync(0xFFFFFFFFu, o1[g], 2);
            o1[g] += __shfl_xor_sync(0xFFFFFFFFu, o1[g], 4);
        }

        if (t8 == 0) {
            #pragma unroll
            for (int g = 0; g < 4; g++) {
                const int e = eb + g * 4 + sub4;
                *(float2*)(out + 2 * (size_t)e) =
                    make_float2(o0[g] + b20, o1[g] + b21);
            }
        }
    }
}

// ---------------------------------------------------------------------------
extern "C" void kernel_launch(void* const* d_in, const int* in_sizes, int n_in,
                              void* d_out, int out_size)
{
    const float* x  = (const float*)d_in[0];      // [N,128]
    const int*   ei = (const int*)d_in[1];        // [2,E] int32
    const float* W1 = (const float*)d_in[2];      // [256,128]
    const float* b1 = (const float*)d_in[3];      // [128]
    const float* W2 = (const float*)d_in[4];      // [128,2]
    const float* b2 = (const float*)d_in[5];      // [2]
    float*       out = (float*)d_out;             // [E,2]

    const int nnodes = in_sizes[0] / ND;
    const int E      = in_sizes[1] / 2;
    const int ntiles = (nnodes + TILE_M - 1) / TILE_M;

    cudaFuncSetAttribute(gemm_kernel, cudaFuncAttributeMaxDynamicSharedMemorySize,
                         SMEM_TOTAL);

    gemm_kernel<<<148, 512, SMEM_TOTAL>>>(x, W1, b1, nnodes, ntiles);
    edge_kernel<<<(E + 63) / 64, 128>>>(ei, W2, b2, out, E);
}